// round 1
// baseline (speedup 1.0000x reference)
#include <cuda_runtime.h>
#include <math.h>

#define BB   16384
#define DIM  1024
#define HID  64
#define TWOD 2048

// ---------------- device scratch (no allocations allowed) ----------------
__device__ float g_z1[BB*HID];
__device__ float g_s1[BB*HID];
__device__ float g_h1[BB*HID];
__device__ float g_s2[BB*HID];
__device__ float g_h3[BB*HID];
__device__ float g_phalf[(size_t)BB*DIM];
__device__ float g_W2T[DIM*HID];
__device__ float g_w2s[HID];
__device__ float g_Gqp[HID*HID];
__device__ float g_invm[DIM];

// ---------------- helpers ----------------
__device__ __forceinline__ float dt_of(const float* dtp){
    float x = __ldg(dtp);
    return 1.0f/(1.0f + expf(-x));
}
__device__ __forceinline__ float gelu_f(float x){
    return x * 0.5f * (1.0f + erff(x * 0.70710678118654752440f));
}
__device__ __forceinline__ float dgelu_f(float x){
    float cdf = 0.5f * (1.0f + erff(x * 0.70710678118654752440f));
    float pdf = 0.39894228040143267794f * expf(-0.5f * x * x);
    return cdf + x * pdf;
}

#define FMA16(acc, xv, wv) do {                          \
    acc[0][0] = fmaf(xv.x, wv.x, acc[0][0]);             \
    acc[0][1] = fmaf(xv.x, wv.y, acc[0][1]);             \
    acc[0][2] = fmaf(xv.x, wv.z, acc[0][2]);             \
    acc[0][3] = fmaf(xv.x, wv.w, acc[0][3]);             \
    acc[1][0] = fmaf(xv.y, wv.x, acc[1][0]);             \
    acc[1][1] = fmaf(xv.y, wv.y, acc[1][1]);             \
    acc[1][2] = fmaf(xv.y, wv.z, acc[1][2]);             \
    acc[1][3] = fmaf(xv.y, wv.w, acc[1][3]);             \
    acc[2][0] = fmaf(xv.z, wv.x, acc[2][0]);             \
    acc[2][1] = fmaf(xv.z, wv.y, acc[2][1]);             \
    acc[2][2] = fmaf(xv.z, wv.z, acc[2][2]);             \
    acc[2][3] = fmaf(xv.z, wv.w, acc[2][3]);             \
    acc[3][0] = fmaf(xv.w, wv.x, acc[3][0]);             \
    acc[3][1] = fmaf(xv.w, wv.y, acc[3][1]);             \
    acc[3][2] = fmaf(xv.w, wv.z, acc[3][2]);             \
    acc[3][3] = fmaf(xv.w, wv.w, acc[3][3]);             \
} while(0)

// 4x4 register tile MMA over KK contraction steps.
// SA: [k][m] (row index m, pad 68), SB: [k][n] (pad 68).
template<int KK>
__device__ __forceinline__ void mmaT(float acc[4][4], const float* SA, const float* SB,
                                     int mi4, int ni4){
    #pragma unroll
    for (int k = 0; k < KK; ++k){
        float4 xv = *(const float4*)(SA + k*68 + mi4);
        float4 wv = *(const float4*)(SB + k*68 + ni4);
        FMA16(acc, xv, wv);
    }
}

// Load a 64x64 row-major tile (row stride 64) TRANSPOSED into S[col][row], pad 68.
__device__ __forceinline__ void loadT64(float* S, const float* __restrict__ src, int t){
    #pragma unroll
    for (int i2 = 0; i2 < 4; ++i2){
        int e = t + i2*256;              // float4 index 0..1023
        int row = e >> 4, c4 = e & 15;
        float4 v = *(const float4*)(src + row*64 + c4*4);
        S[(c4*4+0)*68 + row] = v.x;
        S[(c4*4+1)*68 + row] = v.y;
        S[(c4*4+2)*68 + row] = v.z;
        S[(c4*4+3)*68 + row] = v.w;
    }
}
// Natural copy of 64x64 row-major tile into S[row][col] with pad 68.
__device__ __forceinline__ void loadN64(float* S, const float* __restrict__ src, int t){
    #pragma unroll
    for (int i2 = 0; i2 < 4; ++i2){
        int e = t + i2*256;
        int row = e >> 4, c4 = e & 15;
        float4 v = *(const float4*)(src + row*64 + c4*4);
        *(float4*)(S + row*68 + c4*4) = v;
    }
}

// ---------------- prep: w2s, invm, W2T, Gqp = W1q^T W1p ----------------
__global__ __launch_bounds__(256) void prep_kernel(const float* __restrict__ W1,
                                                   const float* __restrict__ W2,
                                                   const float* __restrict__ mass){
    int b = blockIdx.x, t = threadIdx.x;
    if (b == 0){
        if (t < HID){
            float s = 0.f;
            for (int d = 0; d < DIM; ++d) s += W2[t*DIM + d];
            g_w2s[t] = s;
        }
        for (int i = t; i < DIM; i += 256) g_invm[i] = 1.0f / mass[i];
    } else if (b <= 16){
        int base = (b-1)*4096;
        for (int i = t; i < 4096; i += 256){
            int idx = base + i;
            int j = idx >> 10, d = idx & 1023;
            g_W2T[d*HID + j] = W2[idx];
        }
    } else {
        // blocks 17..20: Gqp rows i0..i0+15
        __shared__ float Xc[64][17];
        __shared__ float Yc[64][68];
        int i0 = (b-17)*16;
        int i_ = t & 15, j4 = (t >> 4) * 4;
        float acc[4] = {0.f,0.f,0.f,0.f};
        for (int kc = 0; kc < DIM; kc += 64){
            for (int e = t; e < 1024; e += 256){
                int k = e >> 4, i = e & 15;
                Xc[k][i] = W1[(kc+k)*HID + i0 + i];
            }
            for (int e = t; e < 1024; e += 256){
                int k = e >> 4, c4 = e & 15;
                float4 v = *(const float4*)(W1 + (size_t)(DIM + kc + k)*HID + c4*4);
                *(float4*)&Yc[k][c4*4] = v;
            }
            __syncthreads();
            #pragma unroll 8
            for (int k = 0; k < 64; ++k){
                float x = Xc[k][i_];
                float4 y = *(const float4*)&Yc[k][j4];
                acc[0] = fmaf(x, y.x, acc[0]);
                acc[1] = fmaf(x, y.y, acc[1]);
                acc[2] = fmaf(x, y.z, acc[2]);
                acc[3] = fmaf(x, y.w, acc[3]);
            }
            __syncthreads();
        }
        #pragma unroll
        for (int jj = 0; jj < 4; ++jj) g_Gqp[(i0+i_)*HID + j4+jj] = acc[jj];
    }
}

// ---------------- kA: z1 = [q p] @ W1 + b1 ; h1, s1 ----------------
__global__ __launch_bounds__(256) void kA(const float* __restrict__ q,
                                          const float* __restrict__ p,
                                          const float* __restrict__ W1,
                                          const float* __restrict__ b1){
    __shared__ float SA[32*68];
    __shared__ float SB[32*68];
    int t = threadIdx.x;
    int r0 = blockIdx.x * 64;
    int mi4 = (t & 15) * 4, ni4 = (t >> 4) * 4;
    float acc[4][4] = {};
    for (int kk = 0; kk < TWOD; kk += 32){
        const float* src = (kk < DIM) ? (q + kk) : (p + (kk - DIM));
        #pragma unroll
        for (int i2 = 0; i2 < 2; ++i2){
            int e = t + i2*256;
            int row = e >> 3, kq = e & 7;
            float4 v = *(const float4*)(src + (size_t)(r0+row)*DIM + kq*4);
            SA[(kq*4+0)*68 + row] = v.x;
            SA[(kq*4+1)*68 + row] = v.y;
            SA[(kq*4+2)*68 + row] = v.z;
            SA[(kq*4+3)*68 + row] = v.w;
        }
        #pragma unroll
        for (int i2 = 0; i2 < 2; ++i2){
            int e = t + i2*256;
            int kr = e >> 4, c4 = e & 15;
            float4 v = *(const float4*)(W1 + (size_t)(kk+kr)*HID + c4*4);
            *(float4*)(SB + kr*68 + c4*4) = v;
        }
        __syncthreads();
        mmaT<32>(acc, SA, SB, mi4, ni4);
        __syncthreads();
    }
    float4 bv  = *(const float4*)(b1 + ni4);
    float4 wsv = *(const float4*)(g_w2s + ni4);
    #pragma unroll
    for (int ii = 0; ii < 4; ++ii){
        int r = r0 + mi4 + ii;
        float z0 = acc[ii][0] + bv.x;
        float z1 = acc[ii][1] + bv.y;
        float z2 = acc[ii][2] + bv.z;
        float z3 = acc[ii][3] + bv.w;
        float4 zf = {z0, z1, z2, z3};
        float4 hf = {gelu_f(z0), gelu_f(z1), gelu_f(z2), gelu_f(z3)};
        float4 sf = {dgelu_f(z0)*wsv.x, dgelu_f(z1)*wsv.y,
                     dgelu_f(z2)*wsv.z, dgelu_f(z3)*wsv.w};
        *(float4*)(g_z1 + r*HID + ni4) = zf;
        *(float4*)(g_h1 + r*HID + ni4) = hf;
        *(float4*)(g_s1 + r*HID + ni4) = sf;
    }
}

// ---------------- kB: dHq1 -> p_half, q_new ; H1 -> out_e (temp) ----------------
__global__ __launch_bounds__(256) void kB(const float* __restrict__ q,
                                          const float* __restrict__ p,
                                          const float* __restrict__ W1,
                                          const float* __restrict__ b2,
                                          const float* __restrict__ dtp,
                                          float* __restrict__ out_q,
                                          float* __restrict__ out_e){
    __shared__ float SA[64*68];
    __shared__ float SB[64*68];
    int t = threadIdx.x;
    int r0 = blockIdx.x * 64, d0 = blockIdx.y * 64;
    int mi4 = (t & 15) * 4, ni4 = (t >> 4) * 4;
    float dt = dt_of(dtp), hdt = 0.5f*dt;

    // phase 1: dHq1[r][d] = sum_j s1[r][j] * W1q[d][j]
    loadT64(SA, g_s1 + r0*HID, t);
    loadT64(SB, W1 + (size_t)d0*HID, t);
    __syncthreads();
    float acc[4][4] = {};
    mmaT<64>(acc, SA, SB, mi4, ni4);
    float4 iv = *(const float4*)(g_invm + d0 + ni4);
    #pragma unroll
    for (int ii = 0; ii < 4; ++ii){
        int r = r0 + mi4 + ii;
        size_t off = (size_t)r*DIM + d0 + ni4;
        float4 pv = *(const float4*)(p + off);
        float4 qv = *(const float4*)(q + off);
        float4 ph, qn;
        ph.x = pv.x - hdt*acc[ii][0];  qn.x = qv.x + dt*iv.x*ph.x;
        ph.y = pv.y - hdt*acc[ii][1];  qn.y = qv.y + dt*iv.y*ph.y;
        ph.z = pv.z - hdt*acc[ii][2];  qn.z = qv.z + dt*iv.z*ph.z;
        ph.w = pv.w - hdt*acc[ii][3];  qn.w = qv.w + dt*iv.w*ph.w;
        *(float4*)(g_phalf + off) = ph;
        *(float4*)(out_q   + off) = qn;
    }
    __syncthreads();

    // phase 2: H1[r][d] = sum_j h1[r][j] * W2T[d][j] + b2[d]
    loadT64(SA, g_h1 + r0*HID, t);
    loadT64(SB, g_W2T + (size_t)d0*HID, t);
    __syncthreads();
    float accH[4][4] = {};
    mmaT<64>(accH, SA, SB, mi4, ni4);
    float4 bv = *(const float4*)(b2 + d0 + ni4);
    #pragma unroll
    for (int ii = 0; ii < 4; ++ii){
        int r = r0 + mi4 + ii;
        size_t off = (size_t)r*DIM + d0 + ni4;
        float4 hv;
        hv.x = accH[ii][0] + bv.x;
        hv.y = accH[ii][1] + bv.y;
        hv.z = accH[ii][2] + bv.z;
        hv.w = accH[ii][3] + bv.w;
        *(float4*)(out_e + off) = hv;
    }
}

// ---------------- kU: u = (phalf/m)@W1q ; z2, s2 ; z3, h3 ----------------
__global__ __launch_bounds__(256) void kU(const float* __restrict__ W1,
                                          const float* __restrict__ dtp){
    __shared__ float SA[64*68];
    __shared__ float SB[64*68];
    int t = threadIdx.x;
    int r0 = blockIdx.x * 64;
    int mi4 = (t & 15) * 4, ni4 = (t >> 4) * 4;
    float dt = dt_of(dtp), hdt = 0.5f*dt;

    float acc[4][4] = {};
    for (int kk = 0; kk < DIM; kk += 32){
        #pragma unroll
        for (int i2 = 0; i2 < 2; ++i2){
            int e = t + i2*256;
            int row = e >> 3, kq = e & 7;
            float4 v  = *(const float4*)(g_phalf + (size_t)(r0+row)*DIM + kk + kq*4);
            float4 im = *(const float4*)(g_invm + kk + kq*4);
            SA[(kq*4+0)*68 + row] = v.x*im.x;
            SA[(kq*4+1)*68 + row] = v.y*im.y;
            SA[(kq*4+2)*68 + row] = v.z*im.z;
            SA[(kq*4+3)*68 + row] = v.w*im.w;
        }
        #pragma unroll
        for (int i2 = 0; i2 < 2; ++i2){
            int e = t + i2*256;
            int kr = e >> 4, c4 = e & 15;
            float4 v = *(const float4*)(W1 + (size_t)(kk+kr)*HID + c4*4);
            *(float4*)(SB + kr*68 + c4*4) = v;
        }
        __syncthreads();
        mmaT<32>(acc, SA, SB, mi4, ni4);
        __syncthreads();
    }

    // corr1 = s1 @ Gqp
    loadT64(SA, g_s1 + r0*HID, t);
    loadN64(SB, g_Gqp, t);
    __syncthreads();
    float corr[4][4] = {};
    mmaT<64>(corr, SA, SB, mi4, ni4);

    float z2v[4][4], s2v[4][4];
    float4 wsv = *(const float4*)(g_w2s + ni4);
    #pragma unroll
    for (int ii = 0; ii < 4; ++ii){
        int r = r0 + mi4 + ii;
        float4 z1v = *(const float4*)(g_z1 + r*HID + ni4);
        z2v[ii][0] = z1v.x + dt*acc[ii][0] - hdt*corr[ii][0];
        z2v[ii][1] = z1v.y + dt*acc[ii][1] - hdt*corr[ii][1];
        z2v[ii][2] = z1v.z + dt*acc[ii][2] - hdt*corr[ii][2];
        z2v[ii][3] = z1v.w + dt*acc[ii][3] - hdt*corr[ii][3];
        s2v[ii][0] = dgelu_f(z2v[ii][0]) * wsv.x;
        s2v[ii][1] = dgelu_f(z2v[ii][1]) * wsv.y;
        s2v[ii][2] = dgelu_f(z2v[ii][2]) * wsv.z;
        s2v[ii][3] = dgelu_f(z2v[ii][3]) * wsv.w;
        float4 sf = {s2v[ii][0], s2v[ii][1], s2v[ii][2], s2v[ii][3]};
        *(float4*)(g_s2 + r*HID + ni4) = sf;
    }
    __syncthreads();
    // scatter s2 transposed into SA: SA[j][row]
    #pragma unroll
    for (int ii = 0; ii < 4; ++ii)
        #pragma unroll
        for (int jj = 0; jj < 4; ++jj)
            SA[(ni4+jj)*68 + (mi4+ii)] = s2v[ii][jj];
    __syncthreads();
    float c3[4][4] = {};
    mmaT<64>(c3, SA, SB, mi4, ni4);
    #pragma unroll
    for (int ii = 0; ii < 4; ++ii){
        int r = r0 + mi4 + ii;
        float z30 = z2v[ii][0] - hdt*c3[ii][0];
        float z31 = z2v[ii][1] - hdt*c3[ii][1];
        float z32 = z2v[ii][2] - hdt*c3[ii][2];
        float z33 = z2v[ii][3] - hdt*c3[ii][3];
        float4 hf = {gelu_f(z30), gelu_f(z31), gelu_f(z32), gelu_f(z33)};
        *(float4*)(g_h3 + r*HID + ni4) = hf;
    }
}

// ---------------- kD: dHq2 -> p_new ; H3 -> energy = |H1 - H3| ----------------
__global__ __launch_bounds__(256) void kD(const float* __restrict__ W1,
                                          const float* __restrict__ b2,
                                          const float* __restrict__ dtp,
                                          float* __restrict__ out_p,
                                          float* __restrict__ out_e){
    __shared__ float SA[64*68];
    __shared__ float SB[64*68];
    int t = threadIdx.x;
    int r0 = blockIdx.x * 64, d0 = blockIdx.y * 64;
    int mi4 = (t & 15) * 4, ni4 = (t >> 4) * 4;
    float dt = dt_of(dtp), hdt = 0.5f*dt;

    loadT64(SA, g_s2 + r0*HID, t);
    loadT64(SB, W1 + (size_t)d0*HID, t);
    __syncthreads();
    float acc[4][4] = {};
    mmaT<64>(acc, SA, SB, mi4, ni4);
    #pragma unroll
    for (int ii = 0; ii < 4; ++ii){
        int r = r0 + mi4 + ii;
        size_t off = (size_t)r*DIM + d0 + ni4;
        float4 ph = *(const float4*)(g_phalf + off);
        float4 pn;
        pn.x = ph.x - hdt*acc[ii][0];
        pn.y = ph.y - hdt*acc[ii][1];
        pn.z = ph.z - hdt*acc[ii][2];
        pn.w = ph.w - hdt*acc[ii][3];
        *(float4*)(out_p + off) = pn;
    }
    __syncthreads();

    loadT64(SA, g_h3 + r0*HID, t);
    loadT64(SB, g_W2T + (size_t)d0*HID, t);
    __syncthreads();
    float accH[4][4] = {};
    mmaT<64>(accH, SA, SB, mi4, ni4);
    float4 bv = *(const float4*)(b2 + d0 + ni4);
    #pragma unroll
    for (int ii = 0; ii < 4; ++ii){
        int r = r0 + mi4 + ii;
        size_t off = (size_t)r*DIM + d0 + ni4;
        float4 h1v = *(const float4*)(out_e + off);   // H1 stored by kB
        float4 ev;
        ev.x = fabsf(h1v.x - (accH[ii][0] + bv.x));
        ev.y = fabsf(h1v.y - (accH[ii][1] + bv.y));
        ev.z = fabsf(h1v.z - (accH[ii][2] + bv.z));
        ev.w = fabsf(h1v.w - (accH[ii][3] + bv.w));
        *(float4*)(out_e + off) = ev;
    }
}

// ---------------- launch ----------------
extern "C" void kernel_launch(void* const* d_in, const int* in_sizes, int n_in,
                              void* d_out, int out_size){
    const float* q    = (const float*)d_in[0];
    const float* p    = (const float*)d_in[1];
    const float* W1   = (const float*)d_in[2];
    const float* b1   = (const float*)d_in[3];
    const float* W2   = (const float*)d_in[4];
    const float* b2   = (const float*)d_in[5];
    const float* mass = (const float*)d_in[6];
    const float* dtp  = (const float*)d_in[7];
    float* out_q = (float*)d_out;
    float* out_p = out_q + (size_t)BB*DIM;
    float* out_e = out_p + (size_t)BB*DIM;

    prep_kernel<<<21, 256>>>(W1, W2, mass);
    kA<<<BB/64, 256>>>(q, p, W1, b1);
    dim3 g2(BB/64, DIM/64);
    kB<<<g2, 256>>>(q, p, W1, b2, dtp, out_q, out_e);
    kU<<<BB/64, 256>>>(W1, dtp);
    kD<<<g2, 256>>>(W1, b2, dtp, out_p, out_e);
}

// round 2
// speedup vs baseline: 1.0013x; 1.0013x over previous
#include <cuda_runtime.h>
#include <math.h>

#define BB   16384
#define DIM  1024
#define HID  64
#define TWOD 2048

// ---------------- device scratch (no allocations allowed) ----------------
__device__ float g_z1[BB*HID];
__device__ float g_s1[BB*HID];
__device__ float g_h1[BB*HID];
__device__ float g_s2[BB*HID];
__device__ float g_h3[BB*HID];
__device__ float g_phalf[(size_t)BB*DIM];
__device__ float g_W2T[DIM*HID];
__device__ float g_w2s[HID];
__device__ float g_Gqp[HID*HID];
__device__ float g_invm[DIM];

// ---------------- helpers ----------------
__device__ __forceinline__ float dt_of(const float* dtp){
    float x = __ldg(dtp);
    return 1.0f/(1.0f + expf(-x));
}
__device__ __forceinline__ float gelu_f(float x){
    return x * 0.5f * (1.0f + erff(x * 0.70710678118654752440f));
}
__device__ __forceinline__ float dgelu_f(float x){
    float cdf = 0.5f * (1.0f + erff(x * 0.70710678118654752440f));
    float pdf = 0.39894228040143267794f * expf(-0.5f * x * x);
    return cdf + x * pdf;
}

#define FMA16(acc, xv, wv) do {                          \
    acc[0][0] = fmaf(xv.x, wv.x, acc[0][0]);             \
    acc[0][1] = fmaf(xv.x, wv.y, acc[0][1]);             \
    acc[0][2] = fmaf(xv.x, wv.z, acc[0][2]);             \
    acc[0][3] = fmaf(xv.x, wv.w, acc[0][3]);             \
    acc[1][0] = fmaf(xv.y, wv.x, acc[1][0]);             \
    acc[1][1] = fmaf(xv.y, wv.y, acc[1][1]);             \
    acc[1][2] = fmaf(xv.y, wv.z, acc[1][2]);             \
    acc[1][3] = fmaf(xv.y, wv.w, acc[1][3]);             \
    acc[2][0] = fmaf(xv.z, wv.x, acc[2][0]);             \
    acc[2][1] = fmaf(xv.z, wv.y, acc[2][1]);             \
    acc[2][2] = fmaf(xv.z, wv.z, acc[2][2]);             \
    acc[2][3] = fmaf(xv.z, wv.w, acc[2][3]);             \
    acc[3][0] = fmaf(xv.w, wv.x, acc[3][0]);             \
    acc[3][1] = fmaf(xv.w, wv.y, acc[3][1]);             \
    acc[3][2] = fmaf(xv.w, wv.z, acc[3][2]);             \
    acc[3][3] = fmaf(xv.w, wv.w, acc[3][3]);             \
} while(0)

// 4x4 register tile MMA over KK contraction steps.
// SA: [k][m] (row index m, pad 68), SB: [k][n] (pad 68).
template<int KK>
__device__ __forceinline__ void mmaT(float acc[4][4], const float* SA, const float* SB,
                                     int mi4, int ni4){
    #pragma unroll
    for (int k = 0; k < KK; ++k){
        float4 xv = *(const float4*)(SA + k*68 + mi4);
        float4 wv = *(const float4*)(SB + k*68 + ni4);
        FMA16(acc, xv, wv);
    }
}

// Load a 64x64 row-major tile (row stride 64) TRANSPOSED into S[col][row], pad 68.
__device__ __forceinline__ void loadT64(float* S, const float* __restrict__ src, int t){
    #pragma unroll
    for (int i2 = 0; i2 < 4; ++i2){
        int e = t + i2*256;              // float4 index 0..1023
        int row = e >> 4, c4 = e & 15;
        float4 v = *(const float4*)(src + row*64 + c4*4);
        S[(c4*4+0)*68 + row] = v.x;
        S[(c4*4+1)*68 + row] = v.y;
        S[(c4*4+2)*68 + row] = v.z;
        S[(c4*4+3)*68 + row] = v.w;
    }
}
// Natural copy of 64x64 row-major tile into S[row][col] with pad 68.
__device__ __forceinline__ void loadN64(float* S, const float* __restrict__ src, int t){
    #pragma unroll
    for (int i2 = 0; i2 < 4; ++i2){
        int e = t + i2*256;
        int row = e >> 4, c4 = e & 15;
        float4 v = *(const float4*)(src + row*64 + c4*4);
        *(float4*)(S + row*68 + c4*4) = v;
    }
}

// ---------------- prep: w2s, invm, W2T, Gqp = W1q^T W1p ----------------
__global__ __launch_bounds__(256) void prep_kernel(const float* __restrict__ W1,
                                                   const float* __restrict__ W2,
                                                   const float* __restrict__ mass){
    int b = blockIdx.x, t = threadIdx.x;
    if (b == 0){
        if (t < HID){
            float s = 0.f;
            for (int d = 0; d < DIM; ++d) s += W2[t*DIM + d];
            g_w2s[t] = s;
        }
        for (int i = t; i < DIM; i += 256) g_invm[i] = 1.0f / mass[i];
    } else if (b <= 16){
        int base = (b-1)*4096;
        for (int i = t; i < 4096; i += 256){
            int idx = base + i;
            int j = idx >> 10, d = idx & 1023;
            g_W2T[d*HID + j] = W2[idx];
        }
    } else {
        // blocks 17..20: Gqp rows i0..i0+15
        __shared__ float Xc[64][17];
        __shared__ float Yc[64][68];
        int i0 = (b-17)*16;
        int i_ = t & 15, j4 = (t >> 4) * 4;
        float acc[4] = {0.f,0.f,0.f,0.f};
        for (int kc = 0; kc < DIM; kc += 64){
            for (int e = t; e < 1024; e += 256){
                int k = e >> 4, i = e & 15;
                Xc[k][i] = W1[(kc+k)*HID + i0 + i];
            }
            for (int e = t; e < 1024; e += 256){
                int k = e >> 4, c4 = e & 15;
                float4 v = *(const float4*)(W1 + (size_t)(DIM + kc + k)*HID + c4*4);
                *(float4*)&Yc[k][c4*4] = v;
            }
            __syncthreads();
            #pragma unroll 8
            for (int k = 0; k < 64; ++k){
                float x = Xc[k][i_];
                float4 y = *(const float4*)&Yc[k][j4];
                acc[0] = fmaf(x, y.x, acc[0]);
                acc[1] = fmaf(x, y.y, acc[1]);
                acc[2] = fmaf(x, y.z, acc[2]);
                acc[3] = fmaf(x, y.w, acc[3]);
            }
            __syncthreads();
        }
        #pragma unroll
        for (int jj = 0; jj < 4; ++jj) g_Gqp[(i0+i_)*HID + j4+jj] = acc[jj];
    }
}

// ---------------- kA: z1 = [q p] @ W1 + b1 ; h1, s1 ----------------
__global__ __launch_bounds__(256) void kA(const float* __restrict__ q,
                                          const float* __restrict__ p,
                                          const float* __restrict__ W1,
                                          const float* __restrict__ b1){
    __shared__ float SA[32*68];
    __shared__ float SB[32*68];
    int t = threadIdx.x;
    int r0 = blockIdx.x * 64;
    int mi4 = (t & 15) * 4, ni4 = (t >> 4) * 4;
    float acc[4][4] = {};
    for (int kk = 0; kk < TWOD; kk += 32){
        const float* src = (kk < DIM) ? (q + kk) : (p + (kk - DIM));
        #pragma unroll
        for (int i2 = 0; i2 < 2; ++i2){
            int e = t + i2*256;
            int row = e >> 3, kq = e & 7;
            float4 v = *(const float4*)(src + (size_t)(r0+row)*DIM + kq*4);
            SA[(kq*4+0)*68 + row] = v.x;
            SA[(kq*4+1)*68 + row] = v.y;
            SA[(kq*4+2)*68 + row] = v.z;
            SA[(kq*4+3)*68 + row] = v.w;
        }
        #pragma unroll
        for (int i2 = 0; i2 < 2; ++i2){
            int e = t + i2*256;
            int kr = e >> 4, c4 = e & 15;
            float4 v = *(const float4*)(W1 + (size_t)(kk+kr)*HID + c4*4);
            *(float4*)(SB + kr*68 + c4*4) = v;
        }
        __syncthreads();
        mmaT<32>(acc, SA, SB, mi4, ni4);
        __syncthreads();
    }
    float4 bv  = *(const float4*)(b1 + ni4);
    float4 wsv = *(const float4*)(g_w2s + ni4);
    #pragma unroll
    for (int ii = 0; ii < 4; ++ii){
        int r = r0 + mi4 + ii;
        float z0 = acc[ii][0] + bv.x;
        float z1 = acc[ii][1] + bv.y;
        float z2 = acc[ii][2] + bv.z;
        float z3 = acc[ii][3] + bv.w;
        float4 zf = {z0, z1, z2, z3};
        float4 hf = {gelu_f(z0), gelu_f(z1), gelu_f(z2), gelu_f(z3)};
        float4 sf = {dgelu_f(z0)*wsv.x, dgelu_f(z1)*wsv.y,
                     dgelu_f(z2)*wsv.z, dgelu_f(z3)*wsv.w};
        *(float4*)(g_z1 + r*HID + ni4) = zf;
        *(float4*)(g_h1 + r*HID + ni4) = hf;
        *(float4*)(g_s1 + r*HID + ni4) = sf;
    }
}

// ---------------- kB: dHq1 -> p_half, q_new ; H1 -> out_e (temp) ----------------
__global__ __launch_bounds__(256) void kB(const float* __restrict__ q,
                                          const float* __restrict__ p,
                                          const float* __restrict__ W1,
                                          const float* __restrict__ b2,
                                          const float* __restrict__ dtp,
                                          float* __restrict__ out_q,
                                          float* __restrict__ out_e){
    __shared__ float SA[64*68];
    __shared__ float SB[64*68];
    int t = threadIdx.x;
    int r0 = blockIdx.x * 64, d0 = blockIdx.y * 64;
    int mi4 = (t & 15) * 4, ni4 = (t >> 4) * 4;
    float dt = dt_of(dtp), hdt = 0.5f*dt;

    // phase 1: dHq1[r][d] = sum_j s1[r][j] * W1q[d][j]
    loadT64(SA, g_s1 + r0*HID, t);
    loadT64(SB, W1 + (size_t)d0*HID, t);
    __syncthreads();
    float acc[4][4] = {};
    mmaT<64>(acc, SA, SB, mi4, ni4);
    float4 iv = *(const float4*)(g_invm + d0 + ni4);
    #pragma unroll
    for (int ii = 0; ii < 4; ++ii){
        int r = r0 + mi4 + ii;
        size_t off = (size_t)r*DIM + d0 + ni4;
        float4 pv = *(const float4*)(p + off);
        float4 qv = *(const float4*)(q + off);
        float4 ph, qn;
        ph.x = pv.x - hdt*acc[ii][0];  qn.x = qv.x + dt*iv.x*ph.x;
        ph.y = pv.y - hdt*acc[ii][1];  qn.y = qv.y + dt*iv.y*ph.y;
        ph.z = pv.z - hdt*acc[ii][2];  qn.z = qv.z + dt*iv.z*ph.z;
        ph.w = pv.w - hdt*acc[ii][3];  qn.w = qv.w + dt*iv.w*ph.w;
        *(float4*)(g_phalf + off) = ph;
        *(float4*)(out_q   + off) = qn;
    }
    __syncthreads();

    // phase 2: H1[r][d] = sum_j h1[r][j] * W2T[d][j] + b2[d]
    loadT64(SA, g_h1 + r0*HID, t);
    loadT64(SB, g_W2T + (size_t)d0*HID, t);
    __syncthreads();
    float accH[4][4] = {};
    mmaT<64>(accH, SA, SB, mi4, ni4);
    float4 bv = *(const float4*)(b2 + d0 + ni4);
    #pragma unroll
    for (int ii = 0; ii < 4; ++ii){
        int r = r0 + mi4 + ii;
        size_t off = (size_t)r*DIM + d0 + ni4;
        float4 hv;
        hv.x = accH[ii][0] + bv.x;
        hv.y = accH[ii][1] + bv.y;
        hv.z = accH[ii][2] + bv.z;
        hv.w = accH[ii][3] + bv.w;
        *(float4*)(out_e + off) = hv;
    }
}

// ---------------- kU: u = (phalf/m)@W1q ; z2, s2 ; z3, h3 ----------------
__global__ __launch_bounds__(256) void kU(const float* __restrict__ W1,
                                          const float* __restrict__ dtp){
    __shared__ float SA[64*68];
    __shared__ float SB[64*68];
    int t = threadIdx.x;
    int r0 = blockIdx.x * 64;
    int mi4 = (t & 15) * 4, ni4 = (t >> 4) * 4;
    float dt = dt_of(dtp), hdt = 0.5f*dt;

    float acc[4][4] = {};
    for (int kk = 0; kk < DIM; kk += 32){
        #pragma unroll
        for (int i2 = 0; i2 < 2; ++i2){
            int e = t + i2*256;
            int row = e >> 3, kq = e & 7;
            float4 v  = *(const float4*)(g_phalf + (size_t)(r0+row)*DIM + kk + kq*4);
            float4 im = *(const float4*)(g_invm + kk + kq*4);
            SA[(kq*4+0)*68 + row] = v.x*im.x;
            SA[(kq*4+1)*68 + row] = v.y*im.y;
            SA[(kq*4+2)*68 + row] = v.z*im.z;
            SA[(kq*4+3)*68 + row] = v.w*im.w;
        }
        #pragma unroll
        for (int i2 = 0; i2 < 2; ++i2){
            int e = t + i2*256;
            int kr = e >> 4, c4 = e & 15;
            float4 v = *(const float4*)(W1 + (size_t)(kk+kr)*HID + c4*4);
            *(float4*)(SB + kr*68 + c4*4) = v;
        }
        __syncthreads();
        mmaT<32>(acc, SA, SB, mi4, ni4);
        __syncthreads();
    }

    // corr1 = s1 @ Gqp
    loadT64(SA, g_s1 + r0*HID, t);
    loadN64(SB, g_Gqp, t);
    __syncthreads();
    float corr[4][4] = {};
    mmaT<64>(corr, SA, SB, mi4, ni4);

    float z2v[4][4], s2v[4][4];
    float4 wsv = *(const float4*)(g_w2s + ni4);
    #pragma unroll
    for (int ii = 0; ii < 4; ++ii){
        int r = r0 + mi4 + ii;
        float4 z1v = *(const float4*)(g_z1 + r*HID + ni4);
        z2v[ii][0] = z1v.x + dt*acc[ii][0] - hdt*corr[ii][0];
        z2v[ii][1] = z1v.y + dt*acc[ii][1] - hdt*corr[ii][1];
        z2v[ii][2] = z1v.z + dt*acc[ii][2] - hdt*corr[ii][2];
        z2v[ii][3] = z1v.w + dt*acc[ii][3] - hdt*corr[ii][3];
        s2v[ii][0] = dgelu_f(z2v[ii][0]) * wsv.x;
        s2v[ii][1] = dgelu_f(z2v[ii][1]) * wsv.y;
        s2v[ii][2] = dgelu_f(z2v[ii][2]) * wsv.z;
        s2v[ii][3] = dgelu_f(z2v[ii][3]) * wsv.w;
        float4 sf = {s2v[ii][0], s2v[ii][1], s2v[ii][2], s2v[ii][3]};
        *(float4*)(g_s2 + r*HID + ni4) = sf;
    }
    __syncthreads();
    // scatter s2 transposed into SA: SA[j][row]
    #pragma unroll
    for (int ii = 0; ii < 4; ++ii)
        #pragma unroll
        for (int jj = 0; jj < 4; ++jj)
            SA[(ni4+jj)*68 + (mi4+ii)] = s2v[ii][jj];
    __syncthreads();
    float c3[4][4] = {};
    mmaT<64>(c3, SA, SB, mi4, ni4);
    #pragma unroll
    for (int ii = 0; ii < 4; ++ii){
        int r = r0 + mi4 + ii;
        float z30 = z2v[ii][0] - hdt*c3[ii][0];
        float z31 = z2v[ii][1] - hdt*c3[ii][1];
        float z32 = z2v[ii][2] - hdt*c3[ii][2];
        float z33 = z2v[ii][3] - hdt*c3[ii][3];
        float4 hf = {gelu_f(z30), gelu_f(z31), gelu_f(z32), gelu_f(z33)};
        *(float4*)(g_h3 + r*HID + ni4) = hf;
    }
}

// ---------------- kD: dHq2 -> p_new ; H3 -> energy = |H1 - H3| ----------------
__global__ __launch_bounds__(256) void kD(const float* __restrict__ W1,
                                          const float* __restrict__ b2,
                                          const float* __restrict__ dtp,
                                          float* __restrict__ out_p,
                                          float* __restrict__ out_e){
    __shared__ float SA[64*68];
    __shared__ float SB[64*68];
    int t = threadIdx.x;
    int r0 = blockIdx.x * 64, d0 = blockIdx.y * 64;
    int mi4 = (t & 15) * 4, ni4 = (t >> 4) * 4;
    float dt = dt_of(dtp), hdt = 0.5f*dt;

    loadT64(SA, g_s2 + r0*HID, t);
    loadT64(SB, W1 + (size_t)d0*HID, t);
    __syncthreads();
    float acc[4][4] = {};
    mmaT<64>(acc, SA, SB, mi4, ni4);
    #pragma unroll
    for (int ii = 0; ii < 4; ++ii){
        int r = r0 + mi4 + ii;
        size_t off = (size_t)r*DIM + d0 + ni4;
        float4 ph = *(const float4*)(g_phalf + off);
        float4 pn;
        pn.x = ph.x - hdt*acc[ii][0];
        pn.y = ph.y - hdt*acc[ii][1];
        pn.z = ph.z - hdt*acc[ii][2];
        pn.w = ph.w - hdt*acc[ii][3];
        *(float4*)(out_p + off) = pn;
    }
    __syncthreads();

    loadT64(SA, g_h3 + r0*HID, t);
    loadT64(SB, g_W2T + (size_t)d0*HID, t);
    __syncthreads();
    float accH[4][4] = {};
    mmaT<64>(accH, SA, SB, mi4, ni4);
    float4 bv = *(const float4*)(b2 + d0 + ni4);
    #pragma unroll
    for (int ii = 0; ii < 4; ++ii){
        int r = r0 + mi4 + ii;
        size_t off = (size_t)r*DIM + d0 + ni4;
        float4 h1v = *(const float4*)(out_e + off);   // H1 stored by kB
        float4 ev;
        ev.x = fabsf(h1v.x - (accH[ii][0] + bv.x));
        ev.y = fabsf(h1v.y - (accH[ii][1] + bv.y));
        ev.z = fabsf(h1v.z - (accH[ii][2] + bv.z));
        ev.w = fabsf(h1v.w - (accH[ii][3] + bv.w));
        *(float4*)(out_e + off) = ev;
    }
}

// ---------------- launch ----------------
extern "C" void kernel_launch(void* const* d_in, const int* in_sizes, int n_in,
                              void* d_out, int out_size){
    const float* q    = (const float*)d_in[0];
    const float* p    = (const float*)d_in[1];
    const float* W1   = (const float*)d_in[2];
    const float* b1   = (const float*)d_in[3];
    const float* W2   = (const float*)d_in[4];
    const float* b2   = (const float*)d_in[5];
    const float* mass = (const float*)d_in[6];
    const float* dtp  = (const float*)d_in[7];
    float* out_q = (float*)d_out;
    float* out_p = out_q + (size_t)BB*DIM;
    float* out_e = out_p + (size_t)BB*DIM;

    prep_kernel<<<21, 256>>>(W1, W2, mass);
    kA<<<BB/64, 256>>>(q, p, W1, b1);
    dim3 g2(BB/64, DIM/64);
    kB<<<g2, 256>>>(q, p, W1, b2, dtp, out_q, out_e);
    kU<<<BB/64, 256>>>(W1, dtp);
    kD<<<g2, 256>>>(W1, b2, dtp, out_p, out_e);
}